// round 11
// baseline (speedup 1.0000x reference)
#include <cuda_runtime.h>
#include <cuda_fp16.h>
#include <cstdint>

#define DMODEL 512
#define NHEAD  8
#define DK     64
#define BATCH  2
#define SEQ    4096
#define MTOT   (BATCH*SEQ)   // 8192

// Scratch (static device arrays — no runtime allocation). All fp16.
__device__ __half g_qh[(size_t)BATCH*NHEAD*SEQ*DK];   // [B,H,S,Dk], *(log2e/8)
__device__ __half g_kh[(size_t)BATCH*NHEAD*SEQ*DK];   // [B,H,S,Dk]
__device__ __half g_vh[(size_t)BATCH*NHEAD*SEQ*DK];   // [B,H,Dk,S] TRANSPOSED
__device__ __half g_att[(size_t)MTOT*DMODEL];         // [B,S,D]
__device__ __half g_rq[(size_t)MTOT*DMODEL];          // fp16 inputs
__device__ __half g_rk[(size_t)MTOT*DMODEL];
__device__ __half g_rv[(size_t)MTOT*DMODEL];
__device__ __half g_rw[(size_t)4*DMODEL*DMODEL];      // fp16 weights

#define ONES2 0x3C003C00u   // half2(1.0, 1.0)

// ---------------------------------------------------------------------------
__device__ __forceinline__ float ex2(float x) {
    float r;
    asm("ex2.approx.ftz.f32 %0, %1;" : "=f"(r) : "f"(x));
    return r;
}

// pack (lo-m, hi-m) into half2, then packed ex2: returns half2(2^(lo-m), 2^(hi-m))
__device__ __forceinline__ uint32_t ex2h2(float lo, float hi, float m) {
    uint32_t h, r;
    asm("cvt.rn.f16x2.f32 %0, %1, %2;" : "=r"(h) : "f"(hi - m), "f"(lo - m));
    asm("ex2.approx.f16x2 %0, %1;" : "=r"(r) : "r"(h));
    return r;
}

__device__ __forceinline__ void mma_f16(float* d, const uint32_t* a,
                                        uint32_t b0, uint32_t b1) {
    asm volatile(
        "mma.sync.aligned.m16n8k16.row.col.f32.f16.f16.f32 "
        "{%0,%1,%2,%3}, {%4,%5,%6,%7}, {%8,%9}, {%0,%1,%2,%3};\n"
        : "+f"(d[0]), "+f"(d[1]), "+f"(d[2]), "+f"(d[3])
        : "r"(a[0]), "r"(a[1]), "r"(a[2]), "r"(a[3]), "r"(b0), "r"(b1));
}

__device__ __forceinline__ void ldsm4(uint32_t& r0, uint32_t& r1,
                                      uint32_t& r2, uint32_t& r3,
                                      uint32_t saddr) {
    asm volatile(
        "ldmatrix.sync.aligned.m8n8.x4.shared.b16 {%0,%1,%2,%3}, [%4];"
        : "=r"(r0), "=r"(r1), "=r"(r2), "=r"(r3) : "r"(saddr));
}

__device__ __forceinline__ void cp16(uint32_t saddr, const void* g) {
    asm volatile("cp.async.cg.shared.global [%0], [%1], 16;\n"
                 :: "r"(saddr), "l"(g));
}
__device__ __forceinline__ void cpcommit() {
    asm volatile("cp.async.commit_group;\n");
}
template<int N> __device__ __forceinline__ void cpwait() {
    asm volatile("cp.async.wait_group %0;\n" :: "n"(N));
}

// ---------------------------------------------------------------------------
// Batched f32 -> f16 conversion (rn)
// ---------------------------------------------------------------------------
__global__ void conv3_kernel(const float4* __restrict__ s0,
                             const float4* __restrict__ s1,
                             const float4* __restrict__ s2,
                             __half2* __restrict__ d0,
                             __half2* __restrict__ d1,
                             __half2* __restrict__ d2, int n4)
{
    const float4* s = (blockIdx.y == 0) ? s0 : (blockIdx.y == 1) ? s1 : s2;
    __half2*      d = (blockIdx.y == 0) ? d0 : (blockIdx.y == 1) ? d1 : d2;
    for (int i = blockIdx.x * blockDim.x + threadIdx.x; i < n4;
         i += gridDim.x * blockDim.x) {
        float4 v = s[i];
        d[i * 2 + 0] = __floats2half2_rn(v.x, v.y);
        d[i * 2 + 1] = __floats2half2_rn(v.z, v.w);
    }
}

__global__ void conv4_kernel(const float4* __restrict__ s0,
                             const float4* __restrict__ s1,
                             const float4* __restrict__ s2,
                             const float4* __restrict__ s3,
                             __half2* __restrict__ dst, int n4)
{
    const float4* s = (blockIdx.y == 0) ? s0 : (blockIdx.y == 1) ? s1
                    : (blockIdx.y == 2) ? s2 : s3;
    __half2* d = dst + (size_t)blockIdx.y * n4 * 2;
    for (int i = blockIdx.x * blockDim.x + threadIdx.x; i < n4;
         i += gridDim.x * blockDim.x) {
        float4 v = s[i];
        d[i * 2 + 0] = __floats2half2_rn(v.x, v.y);
        d[i * 2 + 1] = __floats2half2_rn(v.z, v.w);
    }
}

// ---------------------------------------------------------------------------
// fp16 GEMM core (unchanged): 128x128 tile, k64 stages, 8 warps,
// cp.async double-buffered, ldmatrix.x4 fragments.
// ---------------------------------------------------------------------------
#define HP 72
#define GST (128*HP)
#define GEMM_SMEM (4*GST*2)        // 73728 B

template<int LAYOUT>
__device__ __forceinline__
void gemm_body(const __half* __restrict__ X, const __half* __restrict__ W,
               const float* __restrict__ bias, void* __restrict__ Yv,
               float scale, int m0, int n0, __half* smh)
{
    __half* A = smh;
    const int tid = threadIdx.x, lane = tid & 31, warp = tid >> 5;
    const int g = lane >> 2, tg = lane & 3;
    const int wm = (warp & 3) * 32, wn = (warp >> 2) * 64;
    const uint32_t sA = (uint32_t)__cvta_generic_to_shared(A);
    const uint32_t sB = sA + 2 * GST * 2;
    const int lj  = lane >> 3, lr = lane & 7;
    const int rA8 = (lj & 1) * 8, kA8 = (lj >> 1) * 8;
    const int rB8 = (lj >> 1) * 8, kB8 = (lj & 1) * 8;

#define G_ISSUE(st, k0)                                                        \
    {                                                                          \
        _Pragma("unroll")                                                      \
        for (int i = 0; i < 8; i++) {                                          \
            int c = tid + i * 256;                                             \
            int r = (c >> 3) & 127, ch = c & 7;                                \
            if (c < 1024)                                                      \
                cp16(sA + ((st) * GST + r * HP) * 2 + ch * 16,                 \
                     X + (size_t)(m0 + r) * DMODEL + (k0) + ch * 8);           \
            else                                                               \
                cp16(sB + ((st) * GST + r * HP) * 2 + ch * 16,                 \
                     W + (size_t)(n0 + r) * DMODEL + (k0) + ch * 8);           \
        }                                                                      \
    }

    G_ISSUE(0, 0);  cpcommit();
    G_ISSUE(1, 64); cpcommit();

    float acc[2][8][4];
#pragma unroll
    for (int t = 0; t < 2; t++)
#pragma unroll
        for (int j = 0; j < 8; j++)
#pragma unroll
            for (int c = 0; c < 4; c++) acc[t][j][c] = 0.f;

    for (int kt = 0; kt < 8; kt++) {
        cpwait<1>();
        __syncthreads();
        const uint32_t Ab = sA + (kt & 1) * GST * 2;
        const uint32_t Bb = sB + (kt & 1) * GST * 2;
#pragma unroll
        for (int kc = 0; kc < 4; kc++) {
            uint32_t a[2][4];
#pragma unroll
            for (int t = 0; t < 2; t++) {
                const int row = wm + t * 16 + rA8 + lr;
                const int ko  = kc * 16 + kA8;
                ldsm4(a[t][0], a[t][1], a[t][2], a[t][3],
                      Ab + (row * HP + ko) * 2);
            }
#pragma unroll
            for (int jp = 0; jp < 4; jp++) {
                uint32_t b[4];
                const int row = wn + jp * 16 + rB8 + lr;
                const int ko  = kc * 16 + kB8;
                ldsm4(b[0], b[1], b[2], b[3], Bb + (row * HP + ko) * 2);
                mma_f16(acc[0][2 * jp    ], a[0], b[0], b[1]);
                mma_f16(acc[1][2 * jp    ], a[1], b[0], b[1]);
                mma_f16(acc[0][2 * jp + 1], a[0], b[2], b[3]);
                mma_f16(acc[1][2 * jp + 1], a[1], b[2], b[3]);
            }
        }
        __syncthreads();
        if (kt + 2 < 8) { G_ISSUE(kt & 1, (kt + 2) * 64); }
        cpcommit();
    }

#pragma unroll
    for (int t = 0; t < 2; t++) {
#pragma unroll
        for (int rr = 0; rr < 2; rr++) {
            const int r = m0 + wm + t * 16 + g + rr * 8;
            const int bb = r >> 12, ss = r & 4095;
#pragma unroll
            for (int j = 0; j < 8; j++) {
                const int n = n0 + wn + j * 8 + 2 * tg;
                float2 bi = *(const float2*)&bias[n];
                float v0 = (acc[t][j][rr * 2 + 0] + bi.x) * scale;
                float v1 = (acc[t][j][rr * 2 + 1] + bi.y) * scale;
                if (LAYOUT == 0) {
                    *(float2*)&((float*)Yv)[(size_t)r * DMODEL + n]
                        = make_float2(v0, v1);
                } else if (LAYOUT == 1) {
                    const int h = n >> 6, d = n & 63;
                    *(__half2*)&((__half*)Yv)[
                        (((size_t)(bb * NHEAD + h)) * SEQ + ss) * DK + d]
                        = __floats2half2_rn(v0, v1);
                } else {
                    const int h = n >> 6, d = n & 63;
                    __half* yb = (__half*)Yv
                        + (((size_t)(bb * NHEAD + h)) * DK + d) * SEQ + ss;
                    yb[0]   = __float2half_rn(v0);
                    yb[SEQ] = __float2half_rn(v1);
                }
            }
        }
    }
#undef G_ISSUE
}

__global__ __launch_bounds__(256)
void gemm_qkv(const __half* __restrict__ rq, const __half* __restrict__ rk,
              const __half* __restrict__ rv, const __half* __restrict__ rw,
              const float* __restrict__ bq, const float* __restrict__ bk,
              const float* __restrict__ bv,
              __half* __restrict__ qh, __half* __restrict__ kh,
              __half* __restrict__ vh, float qscale)
{
    extern __shared__ __half smh[];
    const int m0 = blockIdx.y * 128, n0 = blockIdx.x * 128;
    const int DD = DMODEL * DMODEL;
    if (blockIdx.z == 0)
        gemm_body<1>(rq, rw,          bq, qh, qscale, m0, n0, smh);
    else if (blockIdx.z == 1)
        gemm_body<1>(rk, rw + DD,     bk, kh, 1.0f,   m0, n0, smh);
    else
        gemm_body<2>(rv, rw + 2 * DD, bv, vh, 1.0f,   m0, n0, smh);
}

__global__ __launch_bounds__(256)
void gemm_o(const __half* __restrict__ X, const __half* __restrict__ W,
            const float* __restrict__ bias, float* __restrict__ Y)
{
    extern __shared__ __half smh[];
    gemm_body<0>(X, W, bias, Y, 1.0f, blockIdx.y * 128, blockIdx.x * 128, smh);
}

// ---------------------------------------------------------------------------
// fp16 flash attention, MUFU-optimized: ex2.approx.f16x2 (2 exps / MUFU op,
// output IS the packed PV A-fragment) + row-sums via ones-MMA (l = P @ 1,
// no shuffles, exactly consistent with PV's fp16 P).
// 256 thr (8 warps) x 128 query rows, 16 rows/warp, P in registers.
// ---------------------------------------------------------------------------
#define QROWS 128
#define KVB (64*HP)                       // halves per K or V stage
#define SM_K (QROWS*HP)                   // Q buffer first
#define SM_V (SM_K + 2*KVB)
#define ATT_SMEM ((SM_V + 2*KVB)*2)       // 55296 B

__global__ __launch_bounds__(256)
void attn_kernel()
{
    extern __shared__ __half smh[];

    const int bh = blockIdx.y, q0 = blockIdx.x * QROWS;
    const int tid = threadIdx.x, lane = tid & 31, warp = tid >> 5;
    const int w16 = warp * 16;
    const int lj = lane >> 3, lr = lane & 7;
    const int rA8 = (lj & 1) * 8, kA8 = (lj >> 1) * 8;
    const int rB8 = (lj >> 1) * 8, kB8 = (lj & 1) * 8;

    const __half* Qg = g_qh + (size_t)bh * SEQ * DK + (size_t)q0 * DK;
    const __half* Kg = g_kh + (size_t)bh * SEQ * DK;
    const __half* Vg = g_vh + (size_t)bh * DK * SEQ;

    const uint32_t sQ = (uint32_t)__cvta_generic_to_shared(smh);
    const uint32_t sK = sQ + SM_K * 2;
    const uint32_t sV = sQ + SM_V * 2;

    // Q tile: 128 rows x 8 chunks = 1024
#pragma unroll
    for (int i = 0; i < 4; i++) {
        int c = tid + i * 256;
        int row = c >> 3, ch = c & 7;
        cp16(sQ + row * (HP * 2) + ch * 16, Qg + (size_t)row * DK + ch * 8);
    }
    cpcommit();

#define KV_ISSUE(st, ktile)                                                    \
    {                                                                          \
        _Pragma("unroll")                                                      \
        for (int i = 0; i < 4; i++) {                                          \
            int c = tid + i * 256;                                             \
            int r = (c >> 3) & 63, ch = c & 7;                                 \
            if (c < 512)                                                       \
                cp16(sK + (st) * (KVB * 2) + r * (HP * 2) + ch * 16,           \
                     Kg + ((size_t)(ktile) * 64 + r) * DK + ch * 8);           \
            else                                                               \
                cp16(sV + (st) * (KVB * 2) + r * (HP * 2) + ch * 16,           \
                     Vg + (size_t)r * SEQ + (ktile) * 64 + ch * 8);            \
        }                                                                      \
    }

    KV_ISSUE(0, 0); cpcommit();
    KV_ISSUE(1, 1); cpcommit();

    cpwait<2>();
    __syncthreads();

    // Q fragments: 4 k16 chunks
    uint32_t qa[4][4];
#pragma unroll
    for (int kc = 0; kc < 4; kc++) {
        const int row = w16 + rA8 + lr;
        const int ko  = kc * 16 + kA8;
        ldsm4(qa[kc][0], qa[kc][1], qa[kc][2], qa[kc][3],
              sQ + (row * HP + ko) * 2);
    }

    float o[8][4];
    float la[4];                    // l = P @ ones (MMA accumulator)
    float m0 = -1e30f, m1 = -1e30f;
#pragma unroll
    for (int c = 0; c < 4; c++) la[c] = 0.f;
#pragma unroll
    for (int nt = 0; nt < 8; nt++)
#pragma unroll
        for (int c = 0; c < 4; c++) o[nt][c] = 0.f;

    for (int kt = 0; kt < SEQ / 64; kt++) {
        cpwait<1>();
        __syncthreads();
        const uint32_t kbase = sK + (kt & 1) * (KVB * 2);
        const uint32_t vbase = sV + (kt & 1) * (KVB * 2);

        // ---- S = Q @ K^T ----
        float sc[8][4];
#pragma unroll
        for (int nt = 0; nt < 8; nt++)
#pragma unroll
            for (int c = 0; c < 4; c++) sc[nt][c] = 0.f;

#pragma unroll
        for (int kc = 0; kc < 4; kc++) {
#pragma unroll
            for (int np = 0; np < 4; np++) {
                uint32_t b[4];
                const int key = np * 16 + rB8 + lr;
                const int ko  = kc * 16 + kB8;
                ldsm4(b[0], b[1], b[2], b[3], kbase + (key * HP + ko) * 2);
                mma_f16(sc[2 * np    ], qa[kc], b[0], b[1]);
                mma_f16(sc[2 * np + 1], qa[kc], b[2], b[3]);
            }
        }

        // ---- Online softmax: max via shuffles, exp via packed f16x2 ----
        float mx0 = -1e30f, mx1 = -1e30f;
#pragma unroll
        for (int nt = 0; nt < 8; nt++) {
            mx0 = fmaxf(mx0, fmaxf(sc[nt][0], sc[nt][1]));
            mx1 = fmaxf(mx1, fmaxf(sc[nt][2], sc[nt][3]));
        }
        mx0 = fmaxf(mx0, __shfl_xor_sync(0xffffffffu, mx0, 1));
        mx0 = fmaxf(mx0, __shfl_xor_sync(0xffffffffu, mx0, 2));
        mx1 = fmaxf(mx1, __shfl_xor_sync(0xffffffffu, mx1, 1));
        mx1 = fmaxf(mx1, __shfl_xor_sync(0xffffffffu, mx1, 2));

        const float mn0 = fmaxf(m0, mx0), mn1 = fmaxf(m1, mx1);
        const float c0 = ex2(m0 - mn0), c1 = ex2(m1 - mn1);
        m0 = mn0; m1 = mn1;

        // packed P: parr[nt][0] = half2 p(row r, cols 0,1); [1] = row r+8
        uint32_t parr[8][2];
#pragma unroll
        for (int nt = 0; nt < 8; nt++) {
            parr[nt][0] = ex2h2(sc[nt][0], sc[nt][1], mn0);
            parr[nt][1] = ex2h2(sc[nt][2], sc[nt][3], mn1);
        }

        // rescale running O and l
        la[0] *= c0; la[1] *= c0; la[2] *= c1; la[3] *= c1;
#pragma unroll
        for (int nt = 0; nt < 8; nt++) {
            o[nt][0] *= c0; o[nt][1] *= c0;
            o[nt][2] *= c1; o[nt][3] *= c1;
        }

        // ---- O += P @ V ; l += P @ 1 ----
#pragma unroll
        for (int kc = 0; kc < 4; kc++) {
            uint32_t pa[4];
            pa[0] = parr[2 * kc][0];
            pa[1] = parr[2 * kc][1];
            pa[2] = parr[2 * kc + 1][0];
            pa[3] = parr[2 * kc + 1][1];
            mma_f16(la, pa, ONES2, ONES2);     // row sums, no shuffles
#pragma unroll
            for (int np = 0; np < 4; np++) {
                uint32_t b[4];
                const int d  = np * 16 + rB8 + lr;
                const int ko = kc * 16 + kB8;
                ldsm4(b[0], b[1], b[2], b[3], vbase + (d * HP + ko) * 2);
                mma_f16(o[2 * np    ], pa, b[0], b[1]);
                mma_f16(o[2 * np + 1], pa, b[2], b[3]);
            }
        }
        __syncthreads();
        if (kt + 2 < SEQ / 64) { KV_ISSUE(kt & 1, kt + 2); }
        cpcommit();
    }

    // Epilogue: normalize, write fp16 [B,S,D]
    const int g = lane >> 2, tg = lane & 3;
    const int bb = bh >> 3, hh = bh & 7;
    __half* Og = g_att + ((size_t)bb * SEQ + q0) * DMODEL + hh * DK;
    const float inv0 = 1.0f / la[0], inv1 = 1.0f / la[2];
#pragma unroll
    for (int nt = 0; nt < 8; nt++) {
        *(__half2*)&Og[(size_t)(w16 + g    ) * DMODEL + nt * 8 + 2 * tg]
            = __floats2half2_rn(o[nt][0] * inv0, o[nt][1] * inv0);
        *(__half2*)&Og[(size_t)(w16 + g + 8) * DMODEL + nt * 8 + 2 * tg]
            = __floats2half2_rn(o[nt][2] * inv1, o[nt][3] * inv1);
    }
#undef KV_ISSUE
}

// ---------------------------------------------------------------------------
extern "C" void kernel_launch(void* const* d_in, const int* in_sizes, int n_in,
                              void* d_out, int out_size)
{
    const float* q  = (const float*)d_in[0];
    const float* k  = (const float*)d_in[1];
    const float* v  = (const float*)d_in[2];
    const float* wq = (const float*)d_in[3];
    const float* bq = (const float*)d_in[4];
    const float* wk = (const float*)d_in[5];
    const float* bk = (const float*)d_in[6];
    const float* wv = (const float*)d_in[7];
    const float* bv = (const float*)d_in[8];
    const float* wo = (const float*)d_in[9];
    const float* bo = (const float*)d_in[10];

    __half *qh, *kh, *vh, *att, *rq, *rk, *rv, *rw;
    cudaGetSymbolAddress((void**)&qh,  g_qh);
    cudaGetSymbolAddress((void**)&kh,  g_kh);
    cudaGetSymbolAddress((void**)&vh,  g_vh);
    cudaGetSymbolAddress((void**)&att, g_att);
    cudaGetSymbolAddress((void**)&rq,  g_rq);
    cudaGetSymbolAddress((void**)&rk,  g_rk);
    cudaGetSymbolAddress((void**)&rv,  g_rv);
    cudaGetSymbolAddress((void**)&rw,  g_rw);

    cudaFuncSetAttribute(gemm_qkv,
        cudaFuncAttributeMaxDynamicSharedMemorySize, GEMM_SMEM);
    cudaFuncSetAttribute(gemm_o,
        cudaFuncAttributeMaxDynamicSharedMemorySize, GEMM_SMEM);
    cudaFuncSetAttribute(attn_kernel,
        cudaFuncAttributeMaxDynamicSharedMemorySize, ATT_SMEM);

    const int DD = DMODEL * DMODEL;
    const int n4x = MTOT * DMODEL / 4;   // 1048576
    const int n4w = DD / 4;              // 65536

    conv3_kernel<<<dim3(256, 3), 256>>>((const float4*)q, (const float4*)k,
                                        (const float4*)v, (__half2*)rq,
                                        (__half2*)rk, (__half2*)rv, n4x);
    conv4_kernel<<<dim3(128, 4), 256>>>((const float4*)wq, (const float4*)wk,
                                        (const float4*)wv, (const float4*)wo,
                                        (__half2*)rw, n4w);

    const float QSCALE = 0.125f * 1.4426950408889634f;   // 1/sqrt(Dk) * log2e
    gemm_qkv<<<dim3(DMODEL / 128, MTOT / 128, 3), 256, GEMM_SMEM>>>(
        rq, rk, rv, rw, bq, bk, bv, qh, kh, vh, QSCALE);

    attn_kernel<<<dim3(SEQ / QROWS, BATCH * NHEAD), 256, ATT_SMEM>>>();

    gemm_o<<<dim3(DMODEL / 128, MTOT / 128), 256, GEMM_SMEM>>>(
        att, rw + 3 * DD, bo, (float*)d_out);
}

// round 12
// speedup vs baseline: 1.0013x; 1.0013x over previous
#include <cuda_runtime.h>
#include <cuda_fp16.h>
#include <cstdint>

#define DMODEL 512
#define NHEAD  8
#define DK     64
#define BATCH  2
#define SEQ    4096
#define MTOT   (BATCH*SEQ)   // 8192

// Scratch (static device arrays — no runtime allocation). All fp16.
__device__ __half g_qh[(size_t)BATCH*NHEAD*SEQ*DK];   // [B,H,S,Dk], *(log2e/8)
__device__ __half g_kh[(size_t)BATCH*NHEAD*SEQ*DK];   // [B,H,S,Dk]
__device__ __half g_vh[(size_t)BATCH*NHEAD*SEQ*DK];   // [B,H,Dk,S] TRANSPOSED
__device__ __half g_att[(size_t)MTOT*DMODEL];         // [B,S,D]
__device__ __half g_rq[(size_t)MTOT*DMODEL];          // fp16 inputs
__device__ __half g_rk[(size_t)MTOT*DMODEL];
__device__ __half g_rv[(size_t)MTOT*DMODEL];
__device__ __half g_rw[(size_t)4*DMODEL*DMODEL];      // fp16 weights

#define ONES2 0x3C003C00u   // half2(1.0, 1.0)

// ---------------------------------------------------------------------------
__device__ __forceinline__ float ex2(float x) {
    float r;
    asm("ex2.approx.ftz.f32 %0, %1;" : "=f"(r) : "f"(x));
    return r;
}

// pack (lo-m, hi-m) into half2, then packed ex2
__device__ __forceinline__ uint32_t ex2h2(float lo, float hi, float m) {
    uint32_t h, r;
    asm("cvt.rn.f16x2.f32 %0, %1, %2;" : "=r"(h) : "f"(hi - m), "f"(lo - m));
    asm("ex2.approx.f16x2 %0, %1;" : "=r"(r) : "r"(h));
    return r;
}

__device__ __forceinline__ void mma_f16(float* d, const uint32_t* a,
                                        uint32_t b0, uint32_t b1) {
    asm volatile(
        "mma.sync.aligned.m16n8k16.row.col.f32.f16.f16.f32 "
        "{%0,%1,%2,%3}, {%4,%5,%6,%7}, {%8,%9}, {%0,%1,%2,%3};\n"
        : "+f"(d[0]), "+f"(d[1]), "+f"(d[2]), "+f"(d[3])
        : "r"(a[0]), "r"(a[1]), "r"(a[2]), "r"(a[3]), "r"(b0), "r"(b1));
}

__device__ __forceinline__ void ldsm4(uint32_t& r0, uint32_t& r1,
                                      uint32_t& r2, uint32_t& r3,
                                      uint32_t saddr) {
    asm volatile(
        "ldmatrix.sync.aligned.m8n8.x4.shared.b16 {%0,%1,%2,%3}, [%4];"
        : "=r"(r0), "=r"(r1), "=r"(r2), "=r"(r3) : "r"(saddr));
}

__device__ __forceinline__ void cp16(uint32_t saddr, const void* g) {
    asm volatile("cp.async.cg.shared.global [%0], [%1], 16;\n"
                 :: "r"(saddr), "l"(g));
}
__device__ __forceinline__ void cpcommit() {
    asm volatile("cp.async.commit_group;\n");
}
template<int N> __device__ __forceinline__ void cpwait() {
    asm volatile("cp.async.wait_group %0;\n" :: "n"(N));
}

// ---------------------------------------------------------------------------
// Batched f32 -> f16 conversion (rn)
// ---------------------------------------------------------------------------
__global__ void conv3_kernel(const float4* __restrict__ s0,
                             const float4* __restrict__ s1,
                             const float4* __restrict__ s2,
                             __half2* __restrict__ d0,
                             __half2* __restrict__ d1,
                             __half2* __restrict__ d2, int n4)
{
    const float4* s = (blockIdx.y == 0) ? s0 : (blockIdx.y == 1) ? s1 : s2;
    __half2*      d = (blockIdx.y == 0) ? d0 : (blockIdx.y == 1) ? d1 : d2;
    for (int i = blockIdx.x * blockDim.x + threadIdx.x; i < n4;
         i += gridDim.x * blockDim.x) {
        float4 v = s[i];
        d[i * 2 + 0] = __floats2half2_rn(v.x, v.y);
        d[i * 2 + 1] = __floats2half2_rn(v.z, v.w);
    }
}

__global__ void conv4_kernel(const float4* __restrict__ s0,
                             const float4* __restrict__ s1,
                             const float4* __restrict__ s2,
                             const float4* __restrict__ s3,
                             __half2* __restrict__ dst, int n4)
{
    const float4* s = (blockIdx.y == 0) ? s0 : (blockIdx.y == 1) ? s1
                    : (blockIdx.y == 2) ? s2 : s3;
    __half2* d = dst + (size_t)blockIdx.y * n4 * 2;
    for (int i = blockIdx.x * blockDim.x + threadIdx.x; i < n4;
         i += gridDim.x * blockDim.x) {
        float4 v = s[i];
        d[i * 2 + 0] = __floats2half2_rn(v.x, v.y);
        d[i * 2 + 1] = __floats2half2_rn(v.z, v.w);
    }
}

// ---------------------------------------------------------------------------
// fp16 GEMM core (unchanged): 128x128 tile, k64 stages, 8 warps,
// cp.async double-buffered, ldmatrix.x4 fragments.
// ---------------------------------------------------------------------------
#define HP 72
#define GST (128*HP)
#define GEMM_SMEM (4*GST*2)        // 73728 B

template<int LAYOUT>
__device__ __forceinline__
void gemm_body(const __half* __restrict__ X, const __half* __restrict__ W,
               const float* __restrict__ bias, void* __restrict__ Yv,
               float scale, int m0, int n0, __half* smh)
{
    __half* A = smh;
    const int tid = threadIdx.x, lane = tid & 31, warp = tid >> 5;
    const int g = lane >> 2, tg = lane & 3;
    const int wm = (warp & 3) * 32, wn = (warp >> 2) * 64;
    const uint32_t sA = (uint32_t)__cvta_generic_to_shared(A);
    const uint32_t sB = sA + 2 * GST * 2;
    const int lj  = lane >> 3, lr = lane & 7;
    const int rA8 = (lj & 1) * 8, kA8 = (lj >> 1) * 8;
    const int rB8 = (lj >> 1) * 8, kB8 = (lj & 1) * 8;

#define G_ISSUE(st, k0)                                                        \
    {                                                                          \
        _Pragma("unroll")                                                      \
        for (int i = 0; i < 8; i++) {                                          \
            int c = tid + i * 256;                                             \
            int r = (c >> 3) & 127, ch = c & 7;                                \
            if (c < 1024)                                                      \
                cp16(sA + ((st) * GST + r * HP) * 2 + ch * 16,                 \
                     X + (size_t)(m0 + r) * DMODEL + (k0) + ch * 8);           \
            else                                                               \
                cp16(sB + ((st) * GST + r * HP) * 2 + ch * 16,                 \
                     W + (size_t)(n0 + r) * DMODEL + (k0) + ch * 8);           \
        }                                                                      \
    }

    G_ISSUE(0, 0);  cpcommit();
    G_ISSUE(1, 64); cpcommit();

    float acc[2][8][4];
#pragma unroll
    for (int t = 0; t < 2; t++)
#pragma unroll
        for (int j = 0; j < 8; j++)
#pragma unroll
            for (int c = 0; c < 4; c++) acc[t][j][c] = 0.f;

    for (int kt = 0; kt < 8; kt++) {
        cpwait<1>();
        __syncthreads();
        const uint32_t Ab = sA + (kt & 1) * GST * 2;
        const uint32_t Bb = sB + (kt & 1) * GST * 2;
#pragma unroll
        for (int kc = 0; kc < 4; kc++) {
            uint32_t a[2][4];
#pragma unroll
            for (int t = 0; t < 2; t++) {
                const int row = wm + t * 16 + rA8 + lr;
                const int ko  = kc * 16 + kA8;
                ldsm4(a[t][0], a[t][1], a[t][2], a[t][3],
                      Ab + (row * HP + ko) * 2);
            }
#pragma unroll
            for (int jp = 0; jp < 4; jp++) {
                uint32_t b[4];
                const int row = wn + jp * 16 + rB8 + lr;
                const int ko  = kc * 16 + kB8;
                ldsm4(b[0], b[1], b[2], b[3], Bb + (row * HP + ko) * 2);
                mma_f16(acc[0][2 * jp    ], a[0], b[0], b[1]);
                mma_f16(acc[1][2 * jp    ], a[1], b[0], b[1]);
                mma_f16(acc[0][2 * jp + 1], a[0], b[2], b[3]);
                mma_f16(acc[1][2 * jp + 1], a[1], b[2], b[3]);
            }
        }
        __syncthreads();
        if (kt + 2 < 8) { G_ISSUE(kt & 1, (kt + 2) * 64); }
        cpcommit();
    }

#pragma unroll
    for (int t = 0; t < 2; t++) {
#pragma unroll
        for (int rr = 0; rr < 2; rr++) {
            const int r = m0 + wm + t * 16 + g + rr * 8;
            const int bb = r >> 12, ss = r & 4095;
#pragma unroll
            for (int j = 0; j < 8; j++) {
                const int n = n0 + wn + j * 8 + 2 * tg;
                float2 bi = *(const float2*)&bias[n];
                float v0 = (acc[t][j][rr * 2 + 0] + bi.x) * scale;
                float v1 = (acc[t][j][rr * 2 + 1] + bi.y) * scale;
                if (LAYOUT == 0) {
                    *(float2*)&((float*)Yv)[(size_t)r * DMODEL + n]
                        = make_float2(v0, v1);
                } else if (LAYOUT == 1) {
                    const int h = n >> 6, d = n & 63;
                    *(__half2*)&((__half*)Yv)[
                        (((size_t)(bb * NHEAD + h)) * SEQ + ss) * DK + d]
                        = __floats2half2_rn(v0, v1);
                } else {
                    const int h = n >> 6, d = n & 63;
                    __half* yb = (__half*)Yv
                        + (((size_t)(bb * NHEAD + h)) * DK + d) * SEQ + ss;
                    yb[0]   = __float2half_rn(v0);
                    yb[SEQ] = __float2half_rn(v1);
                }
            }
        }
    }
#undef G_ISSUE
}

__global__ __launch_bounds__(256)
void gemm_qkv(const __half* __restrict__ rq, const __half* __restrict__ rk,
              const __half* __restrict__ rv, const __half* __restrict__ rw,
              const float* __restrict__ bq, const float* __restrict__ bk,
              const float* __restrict__ bv,
              __half* __restrict__ qh, __half* __restrict__ kh,
              __half* __restrict__ vh, float qscale)
{
    extern __shared__ __half smh[];
    const int m0 = blockIdx.y * 128, n0 = blockIdx.x * 128;
    const int DD = DMODEL * DMODEL;
    if (blockIdx.z == 0)
        gemm_body<1>(rq, rw,          bq, qh, qscale, m0, n0, smh);
    else if (blockIdx.z == 1)
        gemm_body<1>(rk, rw + DD,     bk, kh, 1.0f,   m0, n0, smh);
    else
        gemm_body<2>(rv, rw + 2 * DD, bv, vh, 1.0f,   m0, n0, smh);
}

__global__ __launch_bounds__(256)
void gemm_o(const __half* __restrict__ X, const __half* __restrict__ W,
            const float* __restrict__ bias, float* __restrict__ Y)
{
    extern __shared__ __half smh[];
    gemm_body<0>(X, W, bias, Y, 1.0f, blockIdx.y * 128, blockIdx.x * 128, smh);
}

// ---------------------------------------------------------------------------
// fp16 flash attention, SOFTWARE-PIPELINED (FA2 style): PV of tile kt-1 is
// issued in iteration kt, interleaved with softmax(kt) — tensor pipe stays
// busy during the softmax dependency chain instead of idling in lockstep.
// 4-stage K/V ring (V of tile kt-1 must survive into iteration kt).
// 256 thr (8 warps) x 128 query rows, 16 rows/warp, P in registers.
// ---------------------------------------------------------------------------
#define QROWS 128
#define NSTG 4
#define KVB (64*HP)                       // halves per K or V stage
#define SM_K (QROWS*HP)                   // after Q buffer
#define SM_V (SM_K + NSTG*KVB)
#define ATT_SMEM ((SM_V + NSTG*KVB)*2)    // 92160 B

__global__ __launch_bounds__(256)
void attn_kernel()
{
    extern __shared__ __half smh[];

    const int bh = blockIdx.y, q0 = blockIdx.x * QROWS;
    const int tid = threadIdx.x, lane = tid & 31, warp = tid >> 5;
    const int w16 = warp * 16;
    const int lj = lane >> 3, lr = lane & 7;
    const int rA8 = (lj & 1) * 8, kA8 = (lj >> 1) * 8;
    const int rB8 = (lj >> 1) * 8, kB8 = (lj & 1) * 8;

    const __half* Qg = g_qh + (size_t)bh * SEQ * DK + (size_t)q0 * DK;
    const __half* Kg = g_kh + (size_t)bh * SEQ * DK;
    const __half* Vg = g_vh + (size_t)bh * DK * SEQ;

    const uint32_t sQ = (uint32_t)__cvta_generic_to_shared(smh);
    const uint32_t sK = sQ + SM_K * 2;
    const uint32_t sV = sQ + SM_V * 2;

    // Q tile: 128 rows x 8 chunks = 1024
#pragma unroll
    for (int i = 0; i < 4; i++) {
        int c = tid + i * 256;
        int row = c >> 3, ch = c & 7;
        cp16(sQ + row * (HP * 2) + ch * 16, Qg + (size_t)row * DK + ch * 8);
    }
    cpcommit();

#define KV_ISSUE(st, ktile)                                                    \
    {                                                                          \
        _Pragma("unroll")                                                      \
        for (int i = 0; i < 4; i++) {                                          \
            int c = tid + i * 256;                                             \
            int r = (c >> 3) & 63, ch = c & 7;                                 \
            if (c < 512)                                                       \
                cp16(sK + (st) * (KVB * 2) + r * (HP * 2) + ch * 16,           \
                     Kg + ((size_t)(ktile) * 64 + r) * DK + ch * 8);           \
            else                                                               \
                cp16(sV + (st) * (KVB * 2) + r * (HP * 2) + ch * 16,           \
                     Vg + (size_t)r * SEQ + (ktile) * 64 + ch * 8);            \
        }                                                                      \
    }

    KV_ISSUE(0, 0); cpcommit();
    KV_ISSUE(1, 1); cpcommit();
    KV_ISSUE(2, 2); cpcommit();

    cpwait<2>();          // Q + stage 0 complete
    __syncthreads();

    // Q fragments: 4 k16 chunks
    uint32_t qa[4][4];
#pragma unroll
    for (int kc = 0; kc < 4; kc++) {
        const int row = w16 + rA8 + lr;
        const int ko  = kc * 16 + kA8;
        ldsm4(qa[kc][0], qa[kc][1], qa[kc][2], qa[kc][3],
              sQ + (row * HP + ko) * 2);
    }

    float o[8][4];
    float la[4];
    float m0 = -1e30f, m1 = -1e30f;
    uint32_t parr[8][2];            // P of previous tile (packed fp16 A-frags)
#pragma unroll
    for (int c = 0; c < 4; c++) la[c] = 0.f;
#pragma unroll
    for (int nt = 0; nt < 8; nt++)
#pragma unroll
        for (int c = 0; c < 4; c++) o[nt][c] = 0.f;

    // QK + softmax helpers as macros over local state ----------------------
#define QK_MMA(kbase, sc)                                                      \
    {                                                                          \
        _Pragma("unroll")                                                      \
        for (int kc = 0; kc < 4; kc++) {                                       \
            _Pragma("unroll")                                                  \
            for (int np = 0; np < 4; np++) {                                   \
                uint32_t b[4];                                                 \
                const int key = np * 16 + rB8 + lr;                            \
                const int ko  = kc * 16 + kB8;                                 \
                ldsm4(b[0], b[1], b[2], b[3], (kbase) + (key * HP + ko) * 2);  \
                mma_f16(sc[2 * np    ], qa[kc], b[0], b[1]);                   \
                mma_f16(sc[2 * np + 1], qa[kc], b[2], b[3]);                   \
            }                                                                  \
        }                                                                      \
    }

    // Prologue: tile 0 (QK + softmax only; nothing to PV yet)
    {
        float sc[8][4];
#pragma unroll
        for (int nt = 0; nt < 8; nt++)
#pragma unroll
            for (int c = 0; c < 4; c++) sc[nt][c] = 0.f;
        QK_MMA(sK, sc);

        float mx0 = -1e30f, mx1 = -1e30f;
#pragma unroll
        for (int nt = 0; nt < 8; nt++) {
            mx0 = fmaxf(mx0, fmaxf(sc[nt][0], sc[nt][1]));
            mx1 = fmaxf(mx1, fmaxf(sc[nt][2], sc[nt][3]));
        }
        mx0 = fmaxf(mx0, __shfl_xor_sync(0xffffffffu, mx0, 1));
        mx0 = fmaxf(mx0, __shfl_xor_sync(0xffffffffu, mx0, 2));
        mx1 = fmaxf(mx1, __shfl_xor_sync(0xffffffffu, mx1, 1));
        mx1 = fmaxf(mx1, __shfl_xor_sync(0xffffffffu, mx1, 2));
        m0 = mx0; m1 = mx1;
#pragma unroll
        for (int nt = 0; nt < 8; nt++) {
            parr[nt][0] = ex2h2(sc[nt][0], sc[nt][1], m0);
            parr[nt][1] = ex2h2(sc[nt][2], sc[nt][3], m1);
        }
        __syncthreads();
        KV_ISSUE(3, 3);
        cpcommit();
    }

    for (int kt = 1; kt < SEQ / 64; kt++) {
        cpwait<2>();
        __syncthreads();
        const uint32_t kbase = sK + (kt & 3) * (KVB * 2);
        const uint32_t vbase = sV + ((kt - 1) & 3) * (KVB * 2);

        // ---- S = Q @ K^T (tile kt) ----
        float sc[8][4];
#pragma unroll
        for (int nt = 0; nt < 8; nt++)
#pragma unroll
            for (int c = 0; c < 4; c++) sc[nt][c] = 0.f;
        QK_MMA(kbase, sc);

        // ---- PV(kt-1): tensor work independent of sc — overlaps softmax ----
#pragma unroll
        for (int kc = 0; kc < 4; kc++) {
            uint32_t pa[4];
            pa[0] = parr[2 * kc][0];
            pa[1] = parr[2 * kc][1];
            pa[2] = parr[2 * kc + 1][0];
            pa[3] = parr[2 * kc + 1][1];
            mma_f16(la, pa, ONES2, ONES2);
#pragma unroll
            for (int np = 0; np < 4; np++) {
                uint32_t b[4];
                const int d  = np * 16 + rB8 + lr;
                const int ko = kc * 16 + kB8;
                ldsm4(b[0], b[1], b[2], b[3], vbase + (d * HP + ko) * 2);
                mma_f16(o[2 * np    ], pa, b[0], b[1]);
                mma_f16(o[2 * np + 1], pa, b[2], b[3]);
            }
        }

        // ---- softmax(kt): ALU/MUFU chain, hides under the PV MMA stream ----
        float mx0 = -1e30f, mx1 = -1e30f;
#pragma unroll
        for (int nt = 0; nt < 8; nt++) {
            mx0 = fmaxf(mx0, fmaxf(sc[nt][0], sc[nt][1]));
            mx1 = fmaxf(mx1, fmaxf(sc[nt][2], sc[nt][3]));
        }
        mx0 = fmaxf(mx0, __shfl_xor_sync(0xffffffffu, mx0, 1));
        mx0 = fmaxf(mx0, __shfl_xor_sync(0xffffffffu, mx0, 2));
        mx1 = fmaxf(mx1, __shfl_xor_sync(0xffffffffu, mx1, 1));
        mx1 = fmaxf(mx1, __shfl_xor_sync(0xffffffffu, mx1, 2));

        const float mn0 = fmaxf(m0, mx0), mn1 = fmaxf(m1, mx1);
        const float c0 = ex2(m0 - mn0), c1 = ex2(m1 - mn1);
        m0 = mn0; m1 = mn1;
#pragma unroll
        for (int nt = 0; nt < 8; nt++) {
            parr[nt][0] = ex2h2(sc[nt][0], sc[nt][1], mn0);
            parr[nt][1] = ex2h2(sc[nt][2], sc[nt][3], mn1);
        }

        // ---- rescale running sums (after PV(kt-1) accumulated) ----
        la[0] *= c0; la[1] *= c0; la[2] *= c1; la[3] *= c1;
#pragma unroll
        for (int nt = 0; nt < 8; nt++) {
            o[nt][0] *= c0; o[nt][1] *= c0;
            o[nt][2] *= c1; o[nt][3] *= c1;
        }

        __syncthreads();   // all warps done reading stage (kt-1)&3 (V) / kt (K)
        if (kt + 3 < SEQ / 64) { KV_ISSUE((kt + 3) & 3, kt + 3); }
        cpcommit();
    }

    // Epilogue: PV of final tile
    {
        const uint32_t vbase = sV + ((SEQ / 64 - 1) & 3) * (KVB * 2);
#pragma unroll
        for (int kc = 0; kc < 4; kc++) {
            uint32_t pa[4];
            pa[0] = parr[2 * kc][0];
            pa[1] = parr[2 * kc][1];
            pa[2] = parr[2 * kc + 1][0];
            pa[3] = parr[2 * kc + 1][1];
            mma_f16(la, pa, ONES2, ONES2);
#pragma unroll
            for (int np = 0; np < 4; np++) {
                uint32_t b[4];
                const int d  = np * 16 + rB8 + lr;
                const int ko = kc * 16 + kB8;
                ldsm4(b[0], b[1], b[2], b[3], vbase + (d * HP + ko) * 2);
                mma_f16(o[2 * np    ], pa, b[0], b[1]);
                mma_f16(o[2 * np + 1], pa, b[2], b[3]);
            }
        }
    }

    // Normalize, write fp16 [B,S,D]
    const int g = lane >> 2, tg = lane & 3;
    const int bb = bh >> 3, hh = bh & 7;
    __half* Og = g_att + ((size_t)bb * SEQ + q0) * DMODEL + hh * DK;
    const float inv0 = 1.0f / la[0], inv1 = 1.0f / la[2];
#pragma unroll
    for (int nt = 0; nt < 8; nt++) {
        *(__half2*)&Og[(size_t)(w16 + g    ) * DMODEL + nt * 8 + 2 * tg]
            = __floats2half2_rn(o[nt][0] * inv0, o[nt][1] * inv0);
        *(__half2*)&Og[(size_t)(w16 + g + 8) * DMODEL + nt * 8 + 2 * tg]
            = __floats2half2_rn(o[nt][2] * inv1, o[nt][3] * inv1);
    }
#undef KV_ISSUE
#undef QK_MMA
}

// ---------------------------------------------------------------------------
extern "C" void kernel_launch(void* const* d_in, const int* in_sizes, int n_in,
                              void* d_out, int out_size)
{
    const float* q  = (const float*)d_in[0];
    const float* k  = (const float*)d_in[1];
    const float* v  = (const float*)d_in[2];
    const float* wq = (const float*)d_in[3];
    const float* bq = (const float*)d_in[4];
    const float* wk = (const float*)d_in[5];
    const float* bk = (const float*)d_in[6];
    const float* wv = (const float*)d_in[7];
    const float* bv = (const float*)d_in[8];
    const float* wo = (const float*)d_in[9];
    const float* bo = (const float*)d_in[10];

    __half *qh, *kh, *vh, *att, *rq, *rk, *rv, *rw;
    cudaGetSymbolAddress((void**)&qh,  g_qh);
    cudaGetSymbolAddress((void**)&kh,  g_kh);
    cudaGetSymbolAddress((void**)&vh,  g_vh);
    cudaGetSymbolAddress((void**)&att, g_att);
    cudaGetSymbolAddress((void**)&rq,  g_rq);
    cudaGetSymbolAddress((void**)&rk,  g_rk);
    cudaGetSymbolAddress((void**)&rv,  g_rv);
    cudaGetSymbolAddress((void**)&rw,  g_rw);

    cudaFuncSetAttribute(gemm_qkv,
        cudaFuncAttributeMaxDynamicSharedMemorySize, GEMM_SMEM);
    cudaFuncSetAttribute(gemm_o,
        cudaFuncAttributeMaxDynamicSharedMemorySize, GEMM_SMEM);
    cudaFuncSetAttribute(attn_kernel,
        cudaFuncAttributeMaxDynamicSharedMemorySize, ATT_SMEM);

    const int DD = DMODEL * DMODEL;
    const int n4x = MTOT * DMODEL / 4;   // 1048576
    const int n4w = DD / 4;              // 65536

    conv3_kernel<<<dim3(256, 3), 256>>>((const float4*)q, (const float4*)k,
                                        (const float4*)v, (__half2*)rq,
                                        (__half2*)rk, (__half2*)rv, n4x);
    conv4_kernel<<<dim3(128, 4), 256>>>((const float4*)wq, (const float4*)wk,
                                        (const float4*)wv, (const float4*)wo,
                                        (__half2*)rw, n4w);

    const float QSCALE = 0.125f * 1.4426950408889634f;   // 1/sqrt(Dk) * log2e
    gemm_qkv<<<dim3(DMODEL / 128, MTOT / 128, 3), 256, GEMM_SMEM>>>(
        rq, rk, rv, rw, bq, bk, bv, qh, kh, vh, QSCALE);

    attn_kernel<<<dim3(SEQ / QROWS, BATCH * NHEAD), 256, ATT_SMEM>>>();

    gemm_o<<<dim3(DMODEL / 128, MTOT / 128), 256, GEMM_SMEM>>>(
        att, rw + 3 * DD, bo, (float*)d_out);
}

// round 13
// speedup vs baseline: 1.0194x; 1.0181x over previous
#include <cuda_runtime.h>
#include <cuda_fp16.h>
#include <cstdint>

#define DMODEL 512
#define NHEAD  8
#define DK     64
#define BATCH  2
#define SEQ    4096
#define MTOT   (BATCH*SEQ)   // 8192

// Scratch (static device arrays — no runtime allocation). All fp16.
__device__ __half g_qh[(size_t)BATCH*NHEAD*SEQ*DK];   // [B,H,S,Dk], *(log2e/8)
__device__ __half g_kh[(size_t)BATCH*NHEAD*SEQ*DK];   // [B,H,S,Dk]
__device__ __half g_vh[(size_t)BATCH*NHEAD*SEQ*DK];   // [B,H,Dk,S] TRANSPOSED
__device__ __half g_att[(size_t)MTOT*DMODEL];         // [B,S,D]
__device__ __half g_rq[(size_t)MTOT*DMODEL];          // fp16 inputs
__device__ __half g_rk[(size_t)MTOT*DMODEL];
__device__ __half g_rv[(size_t)MTOT*DMODEL];
__device__ __half g_rw[(size_t)4*DMODEL*DMODEL];      // fp16 weights

// ---------------------------------------------------------------------------
__device__ __forceinline__ float ex2(float x) {
    float r;
    asm("ex2.approx.ftz.f32 %0, %1;" : "=f"(r) : "f"(x));
    return r;
}

// f32-accumulate MMA (projection GEMMs — long K chains need f32)
__device__ __forceinline__ void mma_f16(float* d, const uint32_t* a,
                                        uint32_t b0, uint32_t b1) {
    asm volatile(
        "mma.sync.aligned.m16n8k16.row.col.f32.f16.f16.f32 "
        "{%0,%1,%2,%3}, {%4,%5,%6,%7}, {%8,%9}, {%0,%1,%2,%3};\n"
        : "+f"(d[0]), "+f"(d[1]), "+f"(d[2]), "+f"(d[3])
        : "r"(a[0]), "r"(a[1]), "r"(a[2]), "r"(a[3]), "r"(b0), "r"(b1));
}

// f16-accumulate MMA (attention — short chains, 2x issue rate hypothesis)
__device__ __forceinline__ void mma_h16(uint32_t* d, const uint32_t* a,
                                        uint32_t b0, uint32_t b1) {
    asm volatile(
        "mma.sync.aligned.m16n8k16.row.col.f16.f16.f16.f16 "
        "{%0,%1}, {%2,%3,%4,%5}, {%6,%7}, {%0,%1};\n"
        : "+r"(d[0]), "+r"(d[1])
        : "r"(a[0]), "r"(a[1]), "r"(a[2]), "r"(a[3]), "r"(b0), "r"(b1));
}

__device__ __forceinline__ void ldsm4(uint32_t& r0, uint32_t& r1,
                                      uint32_t& r2, uint32_t& r3,
                                      uint32_t saddr) {
    asm volatile(
        "ldmatrix.sync.aligned.m8n8.x4.shared.b16 {%0,%1,%2,%3}, [%4];"
        : "=r"(r0), "=r"(r1), "=r"(r2), "=r"(r3) : "r"(saddr));
}

__device__ __forceinline__ uint32_t hmax2u(uint32_t a, uint32_t b) {
    __half2 r = __hmax2(*(__half2*)&a, *(__half2*)&b);
    return *(uint32_t*)&r;
}
// p = ex2(s - m) elementwise on packed half2 (output == PV A-fragment)
__device__ __forceinline__ uint32_t ex2sub(uint32_t s, uint32_t m2) {
    uint32_t d, r;
    asm("sub.f16x2 %0, %1, %2;" : "=r"(d) : "r"(s), "r"(m2));
    asm("ex2.approx.f16x2 %0, %1;" : "=r"(r) : "r"(d));
    return r;
}
__device__ __forceinline__ float2 h2f2(uint32_t v) {
    return __half22float2(*(__half2*)&v);
}

__device__ __forceinline__ void cp16(uint32_t saddr, const void* g) {
    asm volatile("cp.async.cg.shared.global [%0], [%1], 16;\n"
                 :: "r"(saddr), "l"(g));
}
__device__ __forceinline__ void cpcommit() {
    asm volatile("cp.async.commit_group;\n");
}
template<int N> __device__ __forceinline__ void cpwait() {
    asm volatile("cp.async.wait_group %0;\n" :: "n"(N));
}

// ---------------------------------------------------------------------------
// Batched f32 -> f16 conversion (rn)
// ---------------------------------------------------------------------------
__global__ void conv3_kernel(const float4* __restrict__ s0,
                             const float4* __restrict__ s1,
                             const float4* __restrict__ s2,
                             __half2* __restrict__ d0,
                             __half2* __restrict__ d1,
                             __half2* __restrict__ d2, int n4)
{
    const float4* s = (blockIdx.y == 0) ? s0 : (blockIdx.y == 1) ? s1 : s2;
    __half2*      d = (blockIdx.y == 0) ? d0 : (blockIdx.y == 1) ? d1 : d2;
    for (int i = blockIdx.x * blockDim.x + threadIdx.x; i < n4;
         i += gridDim.x * blockDim.x) {
        float4 v = s[i];
        d[i * 2 + 0] = __floats2half2_rn(v.x, v.y);
        d[i * 2 + 1] = __floats2half2_rn(v.z, v.w);
    }
}

__global__ void conv4_kernel(const float4* __restrict__ s0,
                             const float4* __restrict__ s1,
                             const float4* __restrict__ s2,
                             const float4* __restrict__ s3,
                             __half2* __restrict__ dst, int n4)
{
    const float4* s = (blockIdx.y == 0) ? s0 : (blockIdx.y == 1) ? s1
                    : (blockIdx.y == 2) ? s2 : s3;
    __half2* d = dst + (size_t)blockIdx.y * n4 * 2;
    for (int i = blockIdx.x * blockDim.x + threadIdx.x; i < n4;
         i += gridDim.x * blockDim.x) {
        float4 v = s[i];
        d[i * 2 + 0] = __floats2half2_rn(v.x, v.y);
        d[i * 2 + 1] = __floats2half2_rn(v.z, v.w);
    }
}

// ---------------------------------------------------------------------------
// fp16 GEMM core (f32 acc, unchanged from R9): 128x128 tile, k64 stages,
// 8 warps, cp.async double-buffered, ldmatrix.x4 fragments.
// ---------------------------------------------------------------------------
#define HP 72
#define GST (128*HP)
#define GEMM_SMEM (4*GST*2)        // 73728 B

template<int LAYOUT>
__device__ __forceinline__
void gemm_body(const __half* __restrict__ X, const __half* __restrict__ W,
               const float* __restrict__ bias, void* __restrict__ Yv,
               float scale, int m0, int n0, __half* smh)
{
    __half* A = smh;
    const int tid = threadIdx.x, lane = tid & 31, warp = tid >> 5;
    const int g = lane >> 2, tg = lane & 3;
    const int wm = (warp & 3) * 32, wn = (warp >> 2) * 64;
    const uint32_t sA = (uint32_t)__cvta_generic_to_shared(A);
    const uint32_t sB = sA + 2 * GST * 2;
    const int lj  = lane >> 3, lr = lane & 7;
    const int rA8 = (lj & 1) * 8, kA8 = (lj >> 1) * 8;
    const int rB8 = (lj >> 1) * 8, kB8 = (lj & 1) * 8;

#define G_ISSUE(st, k0)                                                        \
    {                                                                          \
        _Pragma("unroll")                                                      \
        for (int i = 0; i < 8; i++) {                                          \
            int c = tid + i * 256;                                             \
            int r = (c >> 3) & 127, ch = c & 7;                                \
            if (c < 1024)                                                      \
                cp16(sA + ((st) * GST + r * HP) * 2 + ch * 16,                 \
                     X + (size_t)(m0 + r) * DMODEL + (k0) + ch * 8);           \
            else                                                               \
                cp16(sB + ((st) * GST + r * HP) * 2 + ch * 16,                 \
                     W + (size_t)(n0 + r) * DMODEL + (k0) + ch * 8);           \
        }                                                                      \
    }

    G_ISSUE(0, 0);  cpcommit();
    G_ISSUE(1, 64); cpcommit();

    float acc[2][8][4];
#pragma unroll
    for (int t = 0; t < 2; t++)
#pragma unroll
        for (int j = 0; j < 8; j++)
#pragma unroll
            for (int c = 0; c < 4; c++) acc[t][j][c] = 0.f;

    for (int kt = 0; kt < 8; kt++) {
        cpwait<1>();
        __syncthreads();
        const uint32_t Ab = sA + (kt & 1) * GST * 2;
        const uint32_t Bb = sB + (kt & 1) * GST * 2;
#pragma unroll
        for (int kc = 0; kc < 4; kc++) {
            uint32_t a[2][4];
#pragma unroll
            for (int t = 0; t < 2; t++) {
                const int row = wm + t * 16 + rA8 + lr;
                const int ko  = kc * 16 + kA8;
                ldsm4(a[t][0], a[t][1], a[t][2], a[t][3],
                      Ab + (row * HP + ko) * 2);
            }
#pragma unroll
            for (int jp = 0; jp < 4; jp++) {
                uint32_t b[4];
                const int row = wn + jp * 16 + rB8 + lr;
                const int ko  = kc * 16 + kB8;
                ldsm4(b[0], b[1], b[2], b[3], Bb + (row * HP + ko) * 2);
                mma_f16(acc[0][2 * jp    ], a[0], b[0], b[1]);
                mma_f16(acc[1][2 * jp    ], a[1], b[0], b[1]);
                mma_f16(acc[0][2 * jp + 1], a[0], b[2], b[3]);
                mma_f16(acc[1][2 * jp + 1], a[1], b[2], b[3]);
            }
        }
        __syncthreads();
        if (kt + 2 < 8) { G_ISSUE(kt & 1, (kt + 2) * 64); }
        cpcommit();
    }

#pragma unroll
    for (int t = 0; t < 2; t++) {
#pragma unroll
        for (int rr = 0; rr < 2; rr++) {
            const int r = m0 + wm + t * 16 + g + rr * 8;
            const int bb = r >> 12, ss = r & 4095;
#pragma unroll
            for (int j = 0; j < 8; j++) {
                const int n = n0 + wn + j * 8 + 2 * tg;
                float2 bi = *(const float2*)&bias[n];
                float v0 = (acc[t][j][rr * 2 + 0] + bi.x) * scale;
                float v1 = (acc[t][j][rr * 2 + 1] + bi.y) * scale;
                if (LAYOUT == 0) {
                    *(float2*)&((float*)Yv)[(size_t)r * DMODEL + n]
                        = make_float2(v0, v1);
                } else if (LAYOUT == 1) {
                    const int h = n >> 6, d = n & 63;
                    *(__half2*)&((__half*)Yv)[
                        (((size_t)(bb * NHEAD + h)) * SEQ + ss) * DK + d]
                        = __floats2half2_rn(v0, v1);
                } else {
                    const int h = n >> 6, d = n & 63;
                    __half* yb = (__half*)Yv
                        + (((size_t)(bb * NHEAD + h)) * DK + d) * SEQ + ss;
                    yb[0]   = __float2half_rn(v0);
                    yb[SEQ] = __float2half_rn(v1);
                }
            }
        }
    }
#undef G_ISSUE
}

__global__ __launch_bounds__(256)
void gemm_qkv(const __half* __restrict__ rq, const __half* __restrict__ rk,
              const __half* __restrict__ rv, const __half* __restrict__ rw,
              const float* __restrict__ bq, const float* __restrict__ bk,
              const float* __restrict__ bv,
              __half* __restrict__ qh, __half* __restrict__ kh,
              __half* __restrict__ vh, float qscale)
{
    extern __shared__ __half smh[];
    const int m0 = blockIdx.y * 128, n0 = blockIdx.x * 128;
    const int DD = DMODEL * DMODEL;
    if (blockIdx.z == 0)
        gemm_body<1>(rq, rw,          bq, qh, qscale, m0, n0, smh);
    else if (blockIdx.z == 1)
        gemm_body<1>(rk, rw + DD,     bk, kh, 1.0f,   m0, n0, smh);
    else
        gemm_body<2>(rv, rw + 2 * DD, bv, vh, 1.0f,   m0, n0, smh);
}

__global__ __launch_bounds__(256)
void gemm_o(const __half* __restrict__ X, const __half* __restrict__ W,
            const float* __restrict__ bias, float* __restrict__ Y)
{
    extern __shared__ __half smh[];
    gemm_body<0>(X, W, bias, Y, 1.0f, blockIdx.y * 128, blockIdx.x * 128, smh);
}

// ---------------------------------------------------------------------------
// fp16 flash attention, f16-ACCUMULATE MMAs (R9 geometry: 256 thr x 256 qrows,
// 32 rows/warp as 2 m16 halves, K/V B-frags shared).
// QK: f16 acc (64-add chain). S C-frag (f16) == PV A-frag: softmax is
// hsub2+ex2.f16x2 IN PLACE. PV: f16 acc per tile, flushed to f32 masters
// each tile together with the online-softmax rescale.
// ---------------------------------------------------------------------------
#define QROWS 256
#define KVB (64*HP)                       // halves per K or V stage
#define SM_K (QROWS*HP)                   // Q buffer first
#define SM_V (SM_K + 2*KVB)
#define ATT_SMEM ((SM_V + 2*KVB)*2)       // 73728 B

__global__ __launch_bounds__(256)
void attn_kernel()
{
    extern __shared__ __half smh[];

    const int bh = blockIdx.y, q0 = blockIdx.x * QROWS;
    const int tid = threadIdx.x, lane = tid & 31, warp = tid >> 5;
    const int w32 = warp * 32;
    const int lj = lane >> 3, lr = lane & 7;
    const int rA8 = (lj & 1) * 8, kA8 = (lj >> 1) * 8;
    const int rB8 = (lj >> 1) * 8, kB8 = (lj & 1) * 8;

    const __half* Qg = g_qh + (size_t)bh * SEQ * DK + (size_t)q0 * DK;
    const __half* Kg = g_kh + (size_t)bh * SEQ * DK;
    const __half* Vg = g_vh + (size_t)bh * DK * SEQ;

    const uint32_t sQ = (uint32_t)__cvta_generic_to_shared(smh);
    const uint32_t sK = sQ + SM_K * 2;
    const uint32_t sV = sQ + SM_V * 2;

    // Q tile: 256 rows x 8 chunks = 2048
#pragma unroll
    for (int i = 0; i < 8; i++) {
        int c = tid + i * 256;
        int row = c >> 3, ch = c & 7;
        cp16(sQ + row * (HP * 2) + ch * 16, Qg + (size_t)row * DK + ch * 8);
    }
    cpcommit();

#define KV_ISSUE(st, ktile)                                                    \
    {                                                                          \
        _Pragma("unroll")                                                      \
        for (int i = 0; i < 4; i++) {                                          \
            int c = tid + i * 256;                                             \
            int r = (c >> 3) & 63, ch = c & 7;                                 \
            if (c < 512)                                                       \
                cp16(sK + (st) * (KVB * 2) + r * (HP * 2) + ch * 16,           \
                     Kg + ((size_t)(ktile) * 64 + r) * DK + ch * 8);           \
            else                                                               \
                cp16(sV + (st) * (KVB * 2) + r * (HP * 2) + ch * 16,           \
                     Vg + (size_t)r * SEQ + (ktile) * 64 + ch * 8);            \
        }                                                                      \
    }

    KV_ISSUE(0, 0); cpcommit();
    KV_ISSUE(1, 1); cpcommit();

    cpwait<2>();
    __syncthreads();

    // Q fragments: 2 halves x 4 k16 chunks
    uint32_t qa[2][4][4];
#pragma unroll
    for (int h = 0; h < 2; h++)
#pragma unroll
        for (int kc = 0; kc < 4; kc++) {
            const int row = w32 + h * 16 + rA8 + lr;
            const int ko  = kc * 16 + kA8;
            ldsm4(qa[h][kc][0], qa[h][kc][1], qa[h][kc][2], qa[h][kc][3],
                  sQ + (row * HP + ko) * 2);
        }

    float o[2][8][4];                 // f32 master accumulators
    float m[2][2], l[2][2];
#pragma unroll
    for (int h = 0; h < 2; h++) {
        m[h][0] = -1e30f; m[h][1] = -1e30f; l[h][0] = 0.f; l[h][1] = 0.f;
#pragma unroll
        for (int nt = 0; nt < 8; nt++)
#pragma unroll
            for (int c = 0; c < 4; c++) o[h][nt][c] = 0.f;
    }

    for (int kt = 0; kt < SEQ / 64; kt++) {
        cpwait<1>();
        __syncthreads();
        const uint32_t kbase = sK + (kt & 1) * (KVB * 2);
        const uint32_t vbase = sV + (kt & 1) * (KVB * 2);

        // ---- S = Q @ K^T (f16 acc): sc[h][nt] = {row g pair, row g+8 pair} ----
        uint32_t sc[2][8][2];
#pragma unroll
        for (int h = 0; h < 2; h++)
#pragma unroll
            for (int nt = 0; nt < 8; nt++) { sc[h][nt][0] = 0; sc[h][nt][1] = 0; }

#pragma unroll
        for (int kc = 0; kc < 4; kc++) {
#pragma unroll
            for (int np = 0; np < 4; np++) {
                uint32_t b[4];
                const int key = np * 16 + rB8 + lr;
                const int ko  = kc * 16 + kB8;
                ldsm4(b[0], b[1], b[2], b[3], kbase + (key * HP + ko) * 2);
                mma_h16(sc[0][2 * np    ], qa[0][kc], b[0], b[1]);
                mma_h16(sc[1][2 * np    ], qa[1][kc], b[0], b[1]);
                mma_h16(sc[0][2 * np + 1], qa[0][kc], b[2], b[3]);
                mma_h16(sc[1][2 * np + 1], qa[1][kc], b[2], b[3]);
            }
        }

        // ---- softmax per half (packed fp16); P overwrites sc in place ----
        float c0f[2], c1f[2];
#pragma unroll
        for (int h = 0; h < 2; h++) {
            uint32_t mx0 = sc[h][0][0], mx1 = sc[h][0][1];
#pragma unroll
            for (int nt = 1; nt < 8; nt++) {
                mx0 = hmax2u(mx0, sc[h][nt][0]);
                mx1 = hmax2u(mx1, sc[h][nt][1]);
            }
            mx0 = hmax2u(mx0, __shfl_xor_sync(0xffffffffu, mx0, 1));
            mx0 = hmax2u(mx0, __shfl_xor_sync(0xffffffffu, mx0, 2));
            mx1 = hmax2u(mx1, __shfl_xor_sync(0xffffffffu, mx1, 1));
            mx1 = hmax2u(mx1, __shfl_xor_sync(0xffffffffu, mx1, 2));
            __half2 h0 = *(__half2*)&mx0, h1 = *(__half2*)&mx1;
            float f0 = fmaxf(__low2float(h0), __high2float(h0));
            float f1 = fmaxf(__low2float(h1), __high2float(h1));

            const float mn0 = fmaxf(m[h][0], f0), mn1 = fmaxf(m[h][1], f1);
            c0f[h] = ex2(m[h][0] - mn0);
            c1f[h] = ex2(m[h][1] - mn1);
            m[h][0] = mn0; m[h][1] = mn1;

            __half2 mn0h = __float2half2_rn(mn0);
            __half2 mn1h = __float2half2_rn(mn1);
            const uint32_t mn0u = *(uint32_t*)&mn0h;
            const uint32_t mn1u = *(uint32_t*)&mn1h;

            float s0 = 0.f, s1 = 0.f;
#pragma unroll
            for (int nt = 0; nt < 8; nt++) {
                sc[h][nt][0] = ex2sub(sc[h][nt][0], mn0u);
                sc[h][nt][1] = ex2sub(sc[h][nt][1], mn1u);
                float2 p0 = h2f2(sc[h][nt][0]);
                float2 p1 = h2f2(sc[h][nt][1]);
                s0 += p0.x + p0.y;
                s1 += p1.x + p1.y;
            }
            s0 += __shfl_xor_sync(0xffffffffu, s0, 1);
            s0 += __shfl_xor_sync(0xffffffffu, s0, 2);
            s1 += __shfl_xor_sync(0xffffffffu, s1, 1);
            s1 += __shfl_xor_sync(0xffffffffu, s1, 2);
            l[h][0] = l[h][0] * c0f[h] + s0;
            l[h][1] = l[h][1] * c1f[h] + s1;
        }

        // ---- PV (f16 acc, fresh per tile); sc IS the A-fragment ----
        uint32_t ov[2][8][2];
#pragma unroll
        for (int h = 0; h < 2; h++)
#pragma unroll
            for (int nt = 0; nt < 8; nt++) { ov[h][nt][0] = 0; ov[h][nt][1] = 0; }

#pragma unroll
        for (int kc = 0; kc < 4; kc++) {
            uint32_t pa[2][4];
#pragma unroll
            for (int h = 0; h < 2; h++) {
                pa[h][0] = sc[h][2 * kc][0];
                pa[h][1] = sc[h][2 * kc][1];
                pa[h][2] = sc[h][2 * kc + 1][0];
                pa[h][3] = sc[h][2 * kc + 1][1];
            }
#pragma unroll
            for (int np = 0; np < 4; np++) {
                uint32_t b[4];
                const int d  = np * 16 + rB8 + lr;
                const int ko = kc * 16 + kB8;
                ldsm4(b[0], b[1], b[2], b[3], vbase + (d * HP + ko) * 2);
                mma_h16(ov[0][2 * np    ], pa[0], b[0], b[1]);
                mma_h16(ov[1][2 * np    ], pa[1], b[0], b[1]);
                mma_h16(ov[0][2 * np + 1], pa[0], b[2], b[3]);
                mma_h16(ov[1][2 * np + 1], pa[1], b[2], b[3]);
            }
        }

        // ---- flush tile PV into f32 masters with online rescale ----
#pragma unroll
        for (int h = 0; h < 2; h++) {
            const float cc0 = c0f[h], cc1 = c1f[h];
#pragma unroll
            for (int nt = 0; nt < 8; nt++) {
                float2 t0 = h2f2(ov[h][nt][0]);
                float2 t1 = h2f2(ov[h][nt][1]);
                o[h][nt][0] = o[h][nt][0] * cc0 + t0.x;
                o[h][nt][1] = o[h][nt][1] * cc0 + t0.y;
                o[h][nt][2] = o[h][nt][2] * cc1 + t1.x;
                o[h][nt][3] = o[h][nt][3] * cc1 + t1.y;
            }
        }
        __syncthreads();
        if (kt + 2 < SEQ / 64) { KV_ISSUE(kt & 1, kt + 2); }
        cpcommit();
    }

    // Epilogue: normalize, write fp16 [B,S,D]
    const int g = lane >> 2, tg = lane & 3;
    const int bb = bh >> 3, hh = bh & 7;
    __half* Og = g_att + ((size_t)bb * SEQ + q0) * DMODEL + hh * DK;
#pragma unroll
    for (int h = 0; h < 2; h++) {
#pragma unroll
        for (int rr = 0; rr < 2; rr++) {
            const float inv = 1.0f / l[h][rr];
            const int row = w32 + h * 16 + g + rr * 8;
#pragma unroll
            for (int nt = 0; nt < 8; nt++) {
                *(__half2*)&Og[(size_t)row * DMODEL + nt * 8 + 2 * tg]
                    = __floats2half2_rn(o[h][nt][rr * 2 + 0] * inv,
                                        o[h][nt][rr * 2 + 1] * inv);
            }
        }
    }
#undef KV_ISSUE
}

// ---------------------------------------------------------------------------
extern "C" void kernel_launch(void* const* d_in, const int* in_sizes, int n_in,
                              void* d_out, int out_size)
{
    const float* q  = (const float*)d_in[0];
    const float* k  = (const float*)d_in[1];
    const float* v  = (const float*)d_in[2];
    const float* wq = (const float*)d_in[3];
    const float* bq = (const float*)d_in[4];
    const float* wk = (const float*)d_in[5];
    const float* bk = (const float*)d_in[6];
    const float* wv = (const float*)d_in[7];
    const float* bv = (const float*)d_in[8];
    const float* wo = (const float*)d_in[9];
    const float* bo = (const float*)d_in[10];

    __half *qh, *kh, *vh, *att, *rq, *rk, *rv, *rw;
    cudaGetSymbolAddress((void**)&qh,  g_qh);
    cudaGetSymbolAddress((void**)&kh,  g_kh);
    cudaGetSymbolAddress((void**)&vh,  g_vh);
    cudaGetSymbolAddress((void**)&att, g_att);
    cudaGetSymbolAddress((void**)&rq,  g_rq);
    cudaGetSymbolAddress((void**)&rk,  g_rk);
    cudaGetSymbolAddress((void**)&rv,  g_rv);
    cudaGetSymbolAddress((void**)&rw,  g_rw);

    cudaFuncSetAttribute(gemm_qkv,
        cudaFuncAttributeMaxDynamicSharedMemorySize, GEMM_SMEM);
    cudaFuncSetAttribute(gemm_o,
        cudaFuncAttributeMaxDynamicSharedMemorySize, GEMM_SMEM);
    cudaFuncSetAttribute(attn_kernel,
        cudaFuncAttributeMaxDynamicSharedMemorySize, ATT_SMEM);

    const int DD = DMODEL * DMODEL;
    const int n4x = MTOT * DMODEL / 4;   // 1048576
    const int n4w = DD / 4;              // 65536

    conv3_kernel<<<dim3(256, 3), 256>>>((const float4*)q, (const float4*)k,
                                        (const float4*)v, (__half2*)rq,
                                        (__half2*)rk, (__half2*)rv, n4x);
    conv4_kernel<<<dim3(128, 4), 256>>>((const float4*)wq, (const float4*)wk,
                                        (const float4*)wv, (const float4*)wo,
                                        (__half2*)rw, n4w);

    const float QSCALE = 0.125f * 1.4426950408889634f;   // 1/sqrt(Dk) * log2e
    gemm_qkv<<<dim3(DMODEL / 128, MTOT / 128, 3), 256, GEMM_SMEM>>>(
        rq, rk, rv, rw, bq, bk, bv, qh, kh, vh, QSCALE);

    attn_kernel<<<dim3(SEQ / QROWS, BATCH * NHEAD), 256, ATT_SMEM>>>();

    gemm_o<<<dim3(DMODEL / 128, MTOT / 128), 256, GEMM_SMEM>>>(
        att, rw + 3 * DD, bo, (float*)d_out);
}

// round 14
// speedup vs baseline: 1.0528x; 1.0327x over previous
#include <cuda_runtime.h>
#include <cuda_fp16.h>
#include <cstdint>

#define DMODEL 512
#define NHEAD  8
#define DK     64
#define BATCH  2
#define SEQ    4096
#define MTOT   (BATCH*SEQ)   // 8192

// Scratch (static device arrays — no runtime allocation). All fp16.
__device__ __half g_qh[(size_t)BATCH*NHEAD*SEQ*DK];   // [B,H,S,Dk], *(log2e/8)
__device__ __half g_kh[(size_t)BATCH*NHEAD*SEQ*DK];   // [B,H,S,Dk]
__device__ __half g_vh[(size_t)BATCH*NHEAD*SEQ*DK];   // [B,H,Dk,S] TRANSPOSED
__device__ __half g_att[(size_t)MTOT*DMODEL];         // [B,S,D]
__device__ __half g_rq[(size_t)MTOT*DMODEL];          // fp16 inputs
__device__ __half g_rk[(size_t)MTOT*DMODEL];
__device__ __half g_rv[(size_t)MTOT*DMODEL];
__device__ __half g_rw[(size_t)4*DMODEL*DMODEL];      // fp16 weights

// ---------------------------------------------------------------------------
__device__ __forceinline__ float ex2(float x) {
    float r;
    asm("ex2.approx.ftz.f32 %0, %1;" : "=f"(r) : "f"(x));
    return r;
}

__device__ __forceinline__ void mma_f16(float* d, const uint32_t* a,
                                        uint32_t b0, uint32_t b1) {
    asm volatile(
        "mma.sync.aligned.m16n8k16.row.col.f32.f16.f16.f32 "
        "{%0,%1,%2,%3}, {%4,%5,%6,%7}, {%8,%9}, {%0,%1,%2,%3};\n"
        : "+f"(d[0]), "+f"(d[1]), "+f"(d[2]), "+f"(d[3])
        : "r"(a[0]), "r"(a[1]), "r"(a[2]), "r"(a[3]), "r"(b0), "r"(b1));
}

__device__ __forceinline__ void ldsm4(uint32_t& r0, uint32_t& r1,
                                      uint32_t& r2, uint32_t& r3,
                                      uint32_t saddr) {
    asm volatile(
        "ldmatrix.sync.aligned.m8n8.x4.shared.b16 {%0,%1,%2,%3}, [%4];"
        : "=r"(r0), "=r"(r1), "=r"(r2), "=r"(r3) : "r"(saddr));
}

__device__ __forceinline__ uint32_t h2(float lo, float hi) {
    __half2 v = __floats2half2_rn(lo, hi);
    return *(uint32_t*)&v;
}

__device__ __forceinline__ void cp16(uint32_t saddr, const void* g) {
    asm volatile("cp.async.cg.shared.global [%0], [%1], 16;\n"
                 :: "r"(saddr), "l"(g));
}
__device__ __forceinline__ void cpcommit() {
    asm volatile("cp.async.commit_group;\n");
}
template<int N> __device__ __forceinline__ void cpwait() {
    asm volatile("cp.async.wait_group %0;\n" :: "n"(N));
}

// ---------------------------------------------------------------------------
// Batched f32 -> f16 conversion (rn)
// ---------------------------------------------------------------------------
__global__ void conv3_kernel(const float4* __restrict__ s0,
                             const float4* __restrict__ s1,
                             const float4* __restrict__ s2,
                             __half2* __restrict__ d0,
                             __half2* __restrict__ d1,
                             __half2* __restrict__ d2, int n4)
{
    const float4* s = (blockIdx.y == 0) ? s0 : (blockIdx.y == 1) ? s1 : s2;
    __half2*      d = (blockIdx.y == 0) ? d0 : (blockIdx.y == 1) ? d1 : d2;
    for (int i = blockIdx.x * blockDim.x + threadIdx.x; i < n4;
         i += gridDim.x * blockDim.x) {
        float4 v = s[i];
        d[i * 2 + 0] = __floats2half2_rn(v.x, v.y);
        d[i * 2 + 1] = __floats2half2_rn(v.z, v.w);
    }
}

__global__ void conv4_kernel(const float4* __restrict__ s0,
                             const float4* __restrict__ s1,
                             const float4* __restrict__ s2,
                             const float4* __restrict__ s3,
                             __half2* __restrict__ dst, int n4)
{
    const float4* s = (blockIdx.y == 0) ? s0 : (blockIdx.y == 1) ? s1
                    : (blockIdx.y == 2) ? s2 : s3;
    __half2* d = dst + (size_t)blockIdx.y * n4 * 2;
    for (int i = blockIdx.x * blockDim.x + threadIdx.x; i < n4;
         i += gridDim.x * blockDim.x) {
        float4 v = s[i];
        d[i * 2 + 0] = __floats2half2_rn(v.x, v.y);
        d[i * 2 + 1] = __floats2half2_rn(v.z, v.w);
    }
}

// ---------------------------------------------------------------------------
// fp16 GEMM core (f32 acc): 128x128 tile, k64 stages (8), 8 warps,
// cp.async double-buffered, ldmatrix.x4 fragments.
// R14: callers use __launch_bounds__(256,2) -> 2 co-resident CTAs/SM kills
// the 2-wave quantization (256 CTAs now fit one wave of 296 slots).
// ---------------------------------------------------------------------------
#define HP 72
#define GST (128*HP)
#define GEMM_SMEM (4*GST*2)        // 73728 B (x2 CTAs = 147KB < 228KB)

template<int LAYOUT>
__device__ __forceinline__
void gemm_body(const __half* __restrict__ X, const __half* __restrict__ W,
               const float* __restrict__ bias, void* __restrict__ Yv,
               float scale, int m0, int n0, __half* smh)
{
    __half* A = smh;
    const int tid = threadIdx.x, lane = tid & 31, warp = tid >> 5;
    const int g = lane >> 2, tg = lane & 3;
    const int wm = (warp & 3) * 32, wn = (warp >> 2) * 64;
    const uint32_t sA = (uint32_t)__cvta_generic_to_shared(A);
    const uint32_t sB = sA + 2 * GST * 2;
    const int lj  = lane >> 3, lr = lane & 7;
    const int rA8 = (lj & 1) * 8, kA8 = (lj >> 1) * 8;
    const int rB8 = (lj >> 1) * 8, kB8 = (lj & 1) * 8;

#define G_ISSUE(st, k0)                                                        \
    {                                                                          \
        _Pragma("unroll")                                                      \
        for (int i = 0; i < 8; i++) {                                          \
            int c = tid + i * 256;                                             \
            int r = (c >> 3) & 127, ch = c & 7;                                \
            if (c < 1024)                                                      \
                cp16(sA + ((st) * GST + r * HP) * 2 + ch * 16,                 \
                     X + (size_t)(m0 + r) * DMODEL + (k0) + ch * 8);           \
            else                                                               \
                cp16(sB + ((st) * GST + r * HP) * 2 + ch * 16,                 \
                     W + (size_t)(n0 + r) * DMODEL + (k0) + ch * 8);           \
        }                                                                      \
    }

    G_ISSUE(0, 0);  cpcommit();
    G_ISSUE(1, 64); cpcommit();

    float acc[2][8][4];
#pragma unroll
    for (int t = 0; t < 2; t++)
#pragma unroll
        for (int j = 0; j < 8; j++)
#pragma unroll
            for (int c = 0; c < 4; c++) acc[t][j][c] = 0.f;

    for (int kt = 0; kt < 8; kt++) {
        cpwait<1>();
        __syncthreads();
        const uint32_t Ab = sA + (kt & 1) * GST * 2;
        const uint32_t Bb = sB + (kt & 1) * GST * 2;
#pragma unroll
        for (int kc = 0; kc < 4; kc++) {
            uint32_t a[2][4];
#pragma unroll
            for (int t = 0; t < 2; t++) {
                const int row = wm + t * 16 + rA8 + lr;
                const int ko  = kc * 16 + kA8;
                ldsm4(a[t][0], a[t][1], a[t][2], a[t][3],
                      Ab + (row * HP + ko) * 2);
            }
#pragma unroll
            for (int jp = 0; jp < 4; jp++) {
                uint32_t b[4];
                const int row = wn + jp * 16 + rB8 + lr;
                const int ko  = kc * 16 + kB8;
                ldsm4(b[0], b[1], b[2], b[3], Bb + (row * HP + ko) * 2);
                mma_f16(acc[0][2 * jp    ], a[0], b[0], b[1]);
                mma_f16(acc[1][2 * jp    ], a[1], b[0], b[1]);
                mma_f16(acc[0][2 * jp + 1], a[0], b[2], b[3]);
                mma_f16(acc[1][2 * jp + 1], a[1], b[2], b[3]);
            }
        }
        __syncthreads();
        if (kt + 2 < 8) { G_ISSUE(kt & 1, (kt + 2) * 64); }
        cpcommit();
    }

#pragma unroll
    for (int t = 0; t < 2; t++) {
#pragma unroll
        for (int rr = 0; rr < 2; rr++) {
            const int r = m0 + wm + t * 16 + g + rr * 8;
            const int bb = r >> 12, ss = r & 4095;
#pragma unroll
            for (int j = 0; j < 8; j++) {
                const int n = n0 + wn + j * 8 + 2 * tg;
                float2 bi = *(const float2*)&bias[n];
                float v0 = (acc[t][j][rr * 2 + 0] + bi.x) * scale;
                float v1 = (acc[t][j][rr * 2 + 1] + bi.y) * scale;
                if (LAYOUT == 0) {
                    *(float2*)&((float*)Yv)[(size_t)r * DMODEL + n]
                        = make_float2(v0, v1);
                } else if (LAYOUT == 1) {
                    const int h = n >> 6, d = n & 63;
                    *(__half2*)&((__half*)Yv)[
                        (((size_t)(bb * NHEAD + h)) * SEQ + ss) * DK + d]
                        = __floats2half2_rn(v0, v1);
                } else {
                    const int h = n >> 6, d = n & 63;
                    __half* yb = (__half*)Yv
                        + (((size_t)(bb * NHEAD + h)) * DK + d) * SEQ + ss;
                    yb[0]   = __float2half_rn(v0);
                    yb[SEQ] = __float2half_rn(v1);
                }
            }
        }
    }
#undef G_ISSUE
}

// Fused QKV projections: blockIdx.z selects input/weight/output.
__global__ __launch_bounds__(256, 2)
void gemm_qkv(const __half* __restrict__ rq, const __half* __restrict__ rk,
              const __half* __restrict__ rv, const __half* __restrict__ rw,
              const float* __restrict__ bq, const float* __restrict__ bk,
              const float* __restrict__ bv,
              __half* __restrict__ qh, __half* __restrict__ kh,
              __half* __restrict__ vh, float qscale)
{
    extern __shared__ __half smh[];
    const int m0 = blockIdx.y * 128, n0 = blockIdx.x * 128;
    const int DD = DMODEL * DMODEL;
    if (blockIdx.z == 0)
        gemm_body<1>(rq, rw,          bq, qh, qscale, m0, n0, smh);
    else if (blockIdx.z == 1)
        gemm_body<1>(rk, rw + DD,     bk, kh, 1.0f,   m0, n0, smh);
    else
        gemm_body<2>(rv, rw + 2 * DD, bv, vh, 1.0f,   m0, n0, smh);
}

// Output projection (fp32 result into d_out)
__global__ __launch_bounds__(256, 2)
void gemm_o(const __half* __restrict__ X, const __half* __restrict__ W,
            const float* __restrict__ bias, float* __restrict__ Y)
{
    extern __shared__ __half smh[];
    gemm_body<0>(X, W, bias, Y, 1.0f, blockIdx.y * 128, blockIdx.x * 128, smh);
}

// ---------------------------------------------------------------------------
// fp16 flash attention (EXACT R9 best: 222us, at the mma.sync rate wall):
// 256 thr (8 warps) x 256 query rows, 32 rows/warp (2 m16 halves, K/V
// fragments shared). P entirely in registers. ldmatrix.x4 fragments.
// Softmax in exp2 domain (log2e folded into Q projection scale).
// ---------------------------------------------------------------------------
#define QROWS 256
#define KVB (64*HP)                       // halves per K or V stage
#define SM_K (QROWS*HP)                   // Q buffer first
#define SM_V (SM_K + 2*KVB)
#define ATT_SMEM ((SM_V + 2*KVB)*2)       // 73728 B

__global__ __launch_bounds__(256)
void attn_kernel()
{
    extern __shared__ __half smh[];

    const int bh = blockIdx.y, q0 = blockIdx.x * QROWS;
    const int tid = threadIdx.x, lane = tid & 31, warp = tid >> 5;
    const int w32 = warp * 32;
    const int lj = lane >> 3, lr = lane & 7;
    const int rA8 = (lj & 1) * 8, kA8 = (lj >> 1) * 8;
    const int rB8 = (lj >> 1) * 8, kB8 = (lj & 1) * 8;

    const __half* Qg = g_qh + (size_t)bh * SEQ * DK + (size_t)q0 * DK;
    const __half* Kg = g_kh + (size_t)bh * SEQ * DK;
    const __half* Vg = g_vh + (size_t)bh * DK * SEQ;

    const uint32_t sQ = (uint32_t)__cvta_generic_to_shared(smh);
    const uint32_t sK = sQ + SM_K * 2;
    const uint32_t sV = sQ + SM_V * 2;

    // Q tile: 256 rows x 8 chunks = 2048
#pragma unroll
    for (int i = 0; i < 8; i++) {
        int c = tid + i * 256;
        int row = c >> 3, ch = c & 7;
        cp16(sQ + row * (HP * 2) + ch * 16, Qg + (size_t)row * DK + ch * 8);
    }
    cpcommit();

#define KV_ISSUE(st, ktile)                                                    \
    {                                                                          \
        _Pragma("unroll")                                                      \
        for (int i = 0; i < 4; i++) {                                          \
            int c = tid + i * 256;                                             \
            int r = (c >> 3) & 63, ch = c & 7;                                 \
            if (c < 512)                                                       \
                cp16(sK + (st) * (KVB * 2) + r * (HP * 2) + ch * 16,           \
                     Kg + ((size_t)(ktile) * 64 + r) * DK + ch * 8);           \
            else                                                               \
                cp16(sV + (st) * (KVB * 2) + r * (HP * 2) + ch * 16,           \
                     Vg + (size_t)r * SEQ + (ktile) * 64 + ch * 8);            \
        }                                                                      \
    }

    KV_ISSUE(0, 0); cpcommit();
    KV_ISSUE(1, 1); cpcommit();

    cpwait<2>();
    __syncthreads();

    // Q fragments via ldmatrix: 2 halves x 4 k16 chunks
    uint32_t qa[2][4][4];
#pragma unroll
    for (int h = 0; h < 2; h++)
#pragma unroll
        for (int kc = 0; kc < 4; kc++) {
            const int row = w32 + h * 16 + rA8 + lr;
            const int ko  = kc * 16 + kA8;
            ldsm4(qa[h][kc][0], qa[h][kc][1], qa[h][kc][2], qa[h][kc][3],
                  sQ + (row * HP + ko) * 2);
        }

    float o[2][8][4];
    float m[2][2], l[2][2];
#pragma unroll
    for (int h = 0; h < 2; h++) {
        m[h][0] = -1e30f; m[h][1] = -1e30f; l[h][0] = 0.f; l[h][1] = 0.f;
#pragma unroll
        for (int nt = 0; nt < 8; nt++)
#pragma unroll
            for (int c = 0; c < 4; c++) o[h][nt][c] = 0.f;
    }

    for (int kt = 0; kt < SEQ / 64; kt++) {
        cpwait<1>();
        __syncthreads();
        const uint32_t kbase = sK + (kt & 1) * (KVB * 2);
        const uint32_t vbase = sV + (kt & 1) * (KVB * 2);

        // ---- S = Q @ K^T ----
        float sc[2][8][4];
#pragma unroll
        for (int h = 0; h < 2; h++)
#pragma unroll
            for (int nt = 0; nt < 8; nt++)
#pragma unroll
                for (int c = 0; c < 4; c++) sc[h][nt][c] = 0.f;

#pragma unroll
        for (int kc = 0; kc < 4; kc++) {
            uint32_t kb[4][4];
#pragma unroll
            for (int np = 0; np < 4; np++) {
                const int key = np * 16 + rB8 + lr;
                const int ko  = kc * 16 + kB8;
                ldsm4(kb[np][0], kb[np][1], kb[np][2], kb[np][3],
                      kbase + (key * HP + ko) * 2);
            }
#pragma unroll
            for (int np = 0; np < 4; np++) {
                mma_f16(sc[0][2 * np    ], qa[0][kc], kb[np][0], kb[np][1]);
                mma_f16(sc[1][2 * np    ], qa[1][kc], kb[np][0], kb[np][1]);
                mma_f16(sc[0][2 * np + 1], qa[0][kc], kb[np][2], kb[np][3]);
                mma_f16(sc[1][2 * np + 1], qa[1][kc], kb[np][2], kb[np][3]);
            }
        }

        // ---- Online softmax (exp2 domain); p overwrites sc ----
#pragma unroll
        for (int h = 0; h < 2; h++) {
            float mx0 = -1e30f, mx1 = -1e30f;
#pragma unroll
            for (int nt = 0; nt < 8; nt++) {
                mx0 = fmaxf(mx0, fmaxf(sc[h][nt][0], sc[h][nt][1]));
                mx1 = fmaxf(mx1, fmaxf(sc[h][nt][2], sc[h][nt][3]));
            }
            mx0 = fmaxf(mx0, __shfl_xor_sync(0xffffffffu, mx0, 1));
            mx0 = fmaxf(mx0, __shfl_xor_sync(0xffffffffu, mx0, 2));
            mx1 = fmaxf(mx1, __shfl_xor_sync(0xffffffffu, mx1, 1));
            mx1 = fmaxf(mx1, __shfl_xor_sync(0xffffffffu, mx1, 2));

            const float mn0 = fmaxf(m[h][0], mx0), mn1 = fmaxf(m[h][1], mx1);
            const float c0 = ex2(m[h][0] - mn0), c1 = ex2(m[h][1] - mn1);
            m[h][0] = mn0; m[h][1] = mn1;

            float s0 = 0.f, s1 = 0.f;
#pragma unroll
            for (int nt = 0; nt < 8; nt++) {
                sc[h][nt][0] = ex2(sc[h][nt][0] - mn0);
                sc[h][nt][1] = ex2(sc[h][nt][1] - mn0);
                sc[h][nt][2] = ex2(sc[h][nt][2] - mn1);
                sc[h][nt][3] = ex2(sc[h][nt][3] - mn1);
                s0 += sc[h][nt][0] + sc[h][nt][1];
                s1 += sc[h][nt][2] + sc[h][nt][3];
            }
            s0 += __shfl_xor_sync(0xffffffffu, s0, 1);
            s0 += __shfl_xor_sync(0xffffffffu, s0, 2);
            s1 += __shfl_xor_sync(0xffffffffu, s1, 1);
            s1 += __shfl_xor_sync(0xffffffffu, s1, 2);
            l[h][0] = l[h][0] * c0 + s0;
            l[h][1] = l[h][1] * c1 + s1;
#pragma unroll
            for (int nt = 0; nt < 8; nt++) {
                o[h][nt][0] *= c0; o[h][nt][1] *= c0;
                o[h][nt][2] *= c1; o[h][nt][3] *= c1;
            }
        }

        // ---- O += P @ V : P packed in registers (C-frag == A-frag) ----
#pragma unroll
        for (int kc = 0; kc < 4; kc++) {
            uint32_t vb[4][4];
#pragma unroll
            for (int np = 0; np < 4; np++) {
                const int d  = np * 16 + rB8 + lr;
                const int ko = kc * 16 + kB8;
                ldsm4(vb[np][0], vb[np][1], vb[np][2], vb[np][3],
                      vbase + (d * HP + ko) * 2);
            }
            const int n0b = 2 * kc, n1b = 2 * kc + 1;
            uint32_t pa0[4], pa1[4];
            pa0[0] = h2(sc[0][n0b][0], sc[0][n0b][1]);
            pa0[1] = h2(sc[0][n0b][2], sc[0][n0b][3]);
            pa0[2] = h2(sc[0][n1b][0], sc[0][n1b][1]);
            pa0[3] = h2(sc[0][n1b][2], sc[0][n1b][3]);
            pa1[0] = h2(sc[1][n0b][0], sc[1][n0b][1]);
            pa1[1] = h2(sc[1][n0b][2], sc[1][n0b][3]);
            pa1[2] = h2(sc[1][n1b][0], sc[1][n1b][1]);
            pa1[3] = h2(sc[1][n1b][2], sc[1][n1b][3]);
#pragma unroll
            for (int np = 0; np < 4; np++) {
                mma_f16(o[0][2 * np    ], pa0, vb[np][0], vb[np][1]);
                mma_f16(o[1][2 * np    ], pa1, vb[np][0], vb[np][1]);
                mma_f16(o[0][2 * np + 1], pa0, vb[np][2], vb[np][3]);
                mma_f16(o[1][2 * np + 1], pa1, vb[np][2], vb[np][3]);
            }
        }
        __syncthreads();   // all warps done with stage before refill
        if (kt + 2 < SEQ / 64) { KV_ISSUE(kt & 1, kt + 2); }
        cpcommit();
    }

    // Epilogue: normalize, write fp16 [B,S,D] (feeds fp16 O-GEMM)
    const int g = lane >> 2, tg = lane & 3;
    const int bb = bh >> 3, hh = bh & 7;
    __half* Og = g_att + ((size_t)bb * SEQ + q0) * DMODEL + hh * DK;
#pragma unroll
    for (int h = 0; h < 2; h++) {
#pragma unroll
        for (int rr = 0; rr < 2; rr++) {
            const float inv = 1.0f / l[h][rr];
            const int row = w32 + h * 16 + g + rr * 8;
#pragma unroll
            for (int nt = 0; nt < 8; nt++) {
                *(__half2*)&Og[(size_t)row * DMODEL + nt * 8 + 2 * tg]
                    = __floats2half2_rn(o[h][nt][rr * 2 + 0] * inv,
                                        o[h][nt][rr * 2 + 1] * inv);
            }
        }
    }
#undef KV_ISSUE
}

// ---------------------------------------------------------------------------
extern "C" void kernel_launch(void* const* d_in, const int* in_sizes, int n_in,
                              void* d_out, int out_size)
{
    const float* q  = (const float*)d_in[0];
    const float* k  = (const float*)d_in[1];
    const float* v  = (const float*)d_in[2];
    const float* wq = (const float*)d_in[3];
    const float* bq = (const float*)d_in[4];
    const float* wk = (const float*)d_in[5];
    const float* bk = (const float*)d_in[6];
    const float* wv = (const float*)d_in[7];
    const float* bv = (const float*)d_in[8];
    const float* wo = (const float*)d_in[9];
    const float* bo = (const float*)d_in[10];

    __half *qh, *kh, *vh, *att, *rq, *rk, *rv, *rw;
    cudaGetSymbolAddress((void**)&qh,  g_qh);
    cudaGetSymbolAddress((void**)&kh,  g_kh);
    cudaGetSymbolAddress((void**)&vh,  g_vh);
    cudaGetSymbolAddress((void**)&att, g_att);
    cudaGetSymbolAddress((void**)&rq,  g_rq);
    cudaGetSymbolAddress((void**)&rk,  g_rk);
    cudaGetSymbolAddress((void**)&rv,  g_rv);
    cudaGetSymbolAddress((void**)&rw,  g_rw);

    cudaFuncSetAttribute(gemm_qkv,
        cudaFuncAttributeMaxDynamicSharedMemorySize, GEMM_SMEM);
    cudaFuncSetAttribute(gemm_o,
        cudaFuncAttributeMaxDynamicSharedMemorySize, GEMM_SMEM);
    cudaFuncSetAttribute(attn_kernel,
        cudaFuncAttributeMaxDynamicSharedMemorySize, ATT_SMEM);

    const int DD = DMODEL * DMODEL;
    const int n4x = MTOT * DMODEL / 4;   // 1048576
    const int n4w = DD / 4;              // 65536

    conv3_kernel<<<dim3(256, 3), 256>>>((const float4*)q, (const float4*)k,
                                        (const float4*)v, (__half2*)rq,
                                        (__half2*)rk, (__half2*)rv, n4x);
    conv4_kernel<<<dim3(128, 4), 256>>>((const float4*)wq, (const float4*)wk,
                                        (const float4*)wv, (const float4*)wo,
                                        (__half2*)rw, n4w);

    const float QSCALE = 0.125f * 1.4426950408889634f;   // 1/sqrt(Dk) * log2e
    gemm_qkv<<<dim3(DMODEL / 128, MTOT / 128, 3), 256, GEMM_SMEM>>>(
        rq, rk, rv, rw, bq, bk, bv, qh, kh, vh, QSCALE);

    attn_kernel<<<dim3(SEQ / QROWS, BATCH * NHEAD), 256, ATT_SMEM>>>();

    gemm_o<<<dim3(DMODEL / 128, MTOT / 128), 256, GEMM_SMEM>>>(
        att, rw + 3 * DD, bo, (float*)d_out);
}